// round 7
// baseline (speedup 1.0000x reference)
#include <cuda_runtime.h>
#include <math.h>

#define ND     256
#define BATCH  65536
#define NROT   32640
#define NCHUNK 32
#define CLEN   (NROT / NCHUNK)   // 1020
#define MATSZ  (ND * ND)

// ---------------- device scratch (static allocation only; no cudaMalloc) ----
__device__ float2 g_cs[2][NROT];            // (cos, sin) per rotation, per matrix
__device__ uchar2 g_ij[NROT];               // (i, j) triu indices
__device__ float  g_pcs[2][ND];             // cos(phases), sin(phases)
__device__ float  g_bufA[2][NCHUNK][MATSZ]; // chunk matrices / tree ping
__device__ float  g_bufB[2][NCHUNK / 2][MATSZ]; // tree pong
__device__ float  g_PQ[2][MATSZ];           // P^T, Q^T stored [k][n]
__device__ float  g_invn2[BATCH];           // 1 / ||x_row||^2

__device__ __forceinline__ int tri_off(int i) { return i * (2 * ND - i - 1) / 2; }

// ---- packed f32x2 helpers (Blackwell; per-lane IEEE RN, identical to FFMA) --
#define PACK2(out, lo, hi) \
  asm("mov.b64 %0, {%1, %2};" : "=l"(out) : "r"(lo), "r"(hi))
#define UNPACK2(lo, hi, in) \
  asm("mov.b64 {%0, %1}, %2;" : "=r"(lo), "=r"(hi) : "l"(in))
#define FMA2(d, a, b, c) \
  asm("fma.rn.f32x2 %0, %1, %2, %3;" : "=l"(d) : "l"(a), "l"(b), "l"(c))

// ---------------- setup: triu indices + sincos of angles ---------------------
__global__ void k_setup(const float* __restrict__ r1, const float* __restrict__ r2,
                        const float* __restrict__ ph) {
  int k = blockIdx.x * blockDim.x + threadIdx.x;
  if (k < NROT) {
    float disc = (2.f * ND - 1.f) * (2.f * ND - 1.f) - 8.f * (float)k;
    int i = (int)floorf(((2.f * ND - 1.f) - sqrtf(fmaxf(disc, 0.f))) * 0.5f);
    if (i < 0) i = 0;
    if (i > ND - 2) i = ND - 2;
    while (i > 0 && tri_off(i) > k) i--;
    while (tri_off(i + 1) <= k) i++;
    int j = k - tri_off(i) + i + 1;
    g_ij[k] = make_uchar2((unsigned char)i, (unsigned char)j);
    float s, c;
    sincosf(r1[k], &s, &c); g_cs[0][k] = make_float2(c, s);
    sincosf(r2[k], &s, &c); g_cs[1][k] = make_float2(c, s);
  }
  if (k < ND) {
    float s, c;
    sincosf(ph[k], &s, &c);
    g_pcs[0][k] = c;
    g_pcs[1][k] = s;
  }
}

// ---------------- chunk kernel: apply CLEN Givens rotations to identity ------
// grid (NCHUNK, 8 col-slices, 2 matrices), block = 1 warp, 32 columns/block.
// Static 32KB smem (no attribute calls). Each thread owns exactly one column:
// no cross-thread smem sharing, so no syncs in the rotation loop. Row i is
// cached in a register: in combinations order, i is non-decreasing and j > i
// always, so the cached row is never touched via smem by another rotation.
__global__ void k_chunk() {
  __shared__ float sm[ND * 32];  // 32 KB static
  int t = threadIdx.x;           // 0..31
  int c = blockIdx.x, h = blockIdx.y, m = blockIdx.z;
  int col = (h << 5) + t;
#pragma unroll 8
  for (int r = 0; r < ND; r++) sm[(r << 5) + t] = (r == col) ? 1.f : 0.f;

  int k0 = c * CLEN, k1 = k0 + CLEN;
  int curi = g_ij[k0].x;
  float mi = sm[(curi << 5) + t];
  const float2* __restrict__ cs_arr = g_cs[m];
  for (int k = k0; k < k1; k++) {
    uchar2 ij = g_ij[k];
    float2 cs = cs_arr[k];
    int i = ij.x, j = ij.y;
    if (i != curi) {                 // uniform branch across warp
      sm[(curi << 5) + t] = mi;
      curi = i;
      mi = sm[(i << 5) + t];
    }
    float mj = sm[(j << 5) + t];
    sm[(j << 5) + t] = cs.y * mi + cs.x * mj;
    mi = cs.x * mi - cs.y * mj;
  }
  sm[(curi << 5) + t] = mi;

  float* o = g_bufA[m][c];
#pragma unroll 4
  for (int r = 0; r < ND; r++) o[r * ND + col] = sm[(r << 5) + t];
}

// ---------------- shared 256x256x256 GEMM tile (64x64 per block) -------------
__device__ __forceinline__ void gemm256_tile(const float* __restrict__ A,
                                             const float* __restrict__ B,
                                             float* __restrict__ D,
                                             const float* __restrict__ ks,
                                             int transD, int tile) {
  __shared__ float As[64][17];   // [m][k] padded
  __shared__ float Bs[16][68];   // [k][n] padded
  int m0 = (tile >> 2) << 6;
  int n0 = (tile & 3) << 6;
  int tid = threadIdx.x, tx = tid & 15, ty = tid >> 4;
  float acc[4][4] = {};
  for (int kk = 0; kk < ND; kk += 16) {
    int row = tid >> 2, kc = (tid & 3) << 2;
    float4 av = *(const float4*)(A + (m0 + row) * ND + kk + kc);
    if (ks) {
      av.x *= ks[kk + kc];     av.y *= ks[kk + kc + 1];
      av.z *= ks[kk + kc + 2]; av.w *= ks[kk + kc + 3];
    }
    As[row][kc] = av.x; As[row][kc + 1] = av.y;
    As[row][kc + 2] = av.z; As[row][kc + 3] = av.w;
    int kr = tid >> 4, nc = (tid & 15) << 2;
    *(float4*)&Bs[kr][nc] = *(const float4*)(B + (kk + kr) * ND + n0 + nc);
    __syncthreads();
#pragma unroll
    for (int k = 0; k < 16; k++) {
      float a[4];
#pragma unroll
      for (int r = 0; r < 4; r++) a[r] = As[ty * 4 + r][k];
      float4 b = *(float4*)&Bs[k][tx * 4];
#pragma unroll
      for (int r = 0; r < 4; r++) {
        acc[r][0] += a[r] * b.x; acc[r][1] += a[r] * b.y;
        acc[r][2] += a[r] * b.z; acc[r][3] += a[r] * b.w;
      }
    }
    __syncthreads();
  }
#pragma unroll
  for (int r = 0; r < 4; r++)
#pragma unroll
    for (int c = 0; c < 4; c++) {
      int mm = m0 + ty * 4 + r, nn = n0 + tx * 4 + c;
      if (!transD) D[mm * ND + nn] = acc[r][c];
      else         D[nn * ND + mm] = acc[r][c];
    }
}

// tree level: out[p] = in[2p+1] @ in[2p]
__global__ void k_gemm_tree(int level) {
  int p = blockIdx.x, tile = blockIdx.y, m = blockIdx.z;
  const float* in = (level & 1) ? &g_bufB[m][0][0] : &g_bufA[m][0][0];
  float* out      = (level & 1) ? &g_bufA[m][0][0] : &g_bufB[m][0][0];
  gemm256_tile(in + (size_t)(2 * p + 1) * MATSZ, in + (size_t)(2 * p) * MATSZ,
               out + (size_t)p * MATSZ, nullptr, 0, tile);
}

// P^T/Q^T: P = M2 @ diag(cos/sin phi) @ M1, stored transposed ([k][n])
__global__ void k_gemm_pq() {
  int tile = blockIdx.y, z = blockIdx.z;
  gemm256_tile(&g_bufB[1][0][0] /*M2*/, &g_bufB[0][0][0] /*M1*/,
               g_PQ[z], g_pcs[z], 1, tile);
}

// ---------------- inverse squared row norms ---------------------------------
__global__ void k_invn2(const float* __restrict__ x) {
  int warp = (blockIdx.x * blockDim.x + threadIdx.x) >> 5;
  int lane = threadIdx.x & 31;
  if (warp >= BATCH) return;
  const float4* xr = (const float4*)(x + (size_t)warp * ND);
  float s = 0.f;
#pragma unroll
  for (int it = 0; it < 2; it++) {
    float4 v = xr[lane + 32 * it];
    s += v.x * v.x + v.y * v.y + v.z * v.z + v.w * v.w;
  }
#pragma unroll
  for (int o = 16; o; o >>= 1) s += __shfl_xor_sync(0xffffffffu, s, o);
  if (lane == 0) g_invn2[warp] = 1.0f / s;
}

// ---------------- fused big GEMM: out = invn2 * ((x@P^T)^2 + (x@Q^T)^2) ------
// Inner loop uses packed fma.rn.f32x2 (2 IEEE-RN FMAs per instruction) to halve
// FMA-pipe issue count; numerics identical to the scalar version.
#define BM 128
#define BN 64
#define BK 32
__global__ __launch_bounds__(256, 2) void k_big(const float* __restrict__ x,
                                                float* __restrict__ out) {
  __shared__ float As[BM][BK + 1];   // [m][k] pitch 33 -> conflict-free STS/LDS
  __shared__ float Bp[BK][BN + 4];   // [k][n] pitch 68
  __shared__ float Bq[BK][BN + 4];
  int b0 = blockIdx.x * BM;
  int n0 = blockIdx.y * BN;
  int tid = threadIdx.x, tx = tid & 15, ty = tid >> 4;
  const float* __restrict__ PT = g_PQ[0];
  const float* __restrict__ QT = g_PQ[1];
  // packed accumulators: [row][half], each holds 2 floats (cols 2h, 2h+1)
  unsigned long long accP[8][2] = {}, accQ[8][2] = {};

  for (int kk = 0; kk < ND; kk += BK) {
#pragma unroll
    for (int it = 0; it < 4; it++) {
      int idx = tid + 256 * it;          // 0..1023 float4s of A tile
      int row = idx >> 3;
      int kc = (idx & 7) << 2;
      float4 v = *(const float4*)(x + (size_t)(b0 + row) * ND + kk + kc);
      As[row][kc] = v.x; As[row][kc + 1] = v.y;
      As[row][kc + 2] = v.z; As[row][kc + 3] = v.w;
    }
#pragma unroll
    for (int it = 0; it < 2; it++) {
      int idx = tid + 256 * it;          // 0..511 float4s per B tile
      int kr = idx >> 4;
      int nc = (idx & 15) << 2;
      *(float4*)&Bp[kr][nc] = *(const float4*)(PT + (kk + kr) * ND + n0 + nc);
      *(float4*)&Bq[kr][nc] = *(const float4*)(QT + (kk + kr) * ND + n0 + nc);
    }
    __syncthreads();
#pragma unroll 4
    for (int k = 0; k < BK; k++) {
      unsigned long long a2[8];
#pragma unroll
      for (int r = 0; r < 8; r++) {
        unsigned int au = __float_as_uint(As[ty * 8 + r][k]);
        PACK2(a2[r], au, au);            // broadcast a into both lanes
      }
      float4 bp = *(float4*)&Bp[k][tx * 4];
      float4 bq = *(float4*)&Bq[k][tx * 4];
      unsigned long long bp01, bp23, bq01, bq23;
      PACK2(bp01, __float_as_uint(bp.x), __float_as_uint(bp.y));
      PACK2(bp23, __float_as_uint(bp.z), __float_as_uint(bp.w));
      PACK2(bq01, __float_as_uint(bq.x), __float_as_uint(bq.y));
      PACK2(bq23, __float_as_uint(bq.z), __float_as_uint(bq.w));
#pragma unroll
      for (int r = 0; r < 8; r++) {
        FMA2(accP[r][0], a2[r], bp01, accP[r][0]);
        FMA2(accP[r][1], a2[r], bp23, accP[r][1]);
        FMA2(accQ[r][0], a2[r], bq01, accQ[r][0]);
        FMA2(accQ[r][1], a2[r], bq23, accQ[r][1]);
      }
    }
    __syncthreads();
  }

#pragma unroll
  for (int r = 0; r < 8; r++) {
    int b = b0 + ty * 8 + r;
    float sc = g_invn2[b];
    unsigned int p0u, p1u, p2u, p3u, q0u, q1u, q2u, q3u;
    UNPACK2(p0u, p1u, accP[r][0]);
    UNPACK2(p2u, p3u, accP[r][1]);
    UNPACK2(q0u, q1u, accQ[r][0]);
    UNPACK2(q2u, q3u, accQ[r][1]);
    float p0 = __uint_as_float(p0u), p1 = __uint_as_float(p1u);
    float p2 = __uint_as_float(p2u), p3 = __uint_as_float(p3u);
    float q0 = __uint_as_float(q0u), q1 = __uint_as_float(q1u);
    float q2 = __uint_as_float(q2u), q3 = __uint_as_float(q3u);
    float4 o;
    o.x = (p0 * p0 + q0 * q0) * sc;
    o.y = (p1 * p1 + q1 * q1) * sc;
    o.z = (p2 * p2 + q2 * q2) * sc;
    o.w = (p3 * p3 + q3 * q3) * sc;
    *(float4*)(out + (size_t)b * ND + n0 + tx * 4) = o;
  }
}

// ---------------- launch -----------------------------------------------------
extern "C" void kernel_launch(void* const* d_in, const int* in_sizes, int n_in,
                              void* d_out, int out_size) {
  const float* x     = (const float*)d_in[0];
  const float* rots1 = (const float*)d_in[1];
  const float* ph    = (const float*)d_in[2];
  const float* rots2 = (const float*)d_in[3];
  float* out = (float*)d_out;

  k_setup<<<(NROT + 255) / 256, 256>>>(rots1, rots2, ph);
  k_chunk<<<dim3(NCHUNK, 8, 2), 32>>>();

  int np = NCHUNK / 2, level = 0;
  while (np >= 1) {
    k_gemm_tree<<<dim3(np, 16, 2), 256>>>(level);
    np >>= 1;
    level++;
  }
  k_gemm_pq<<<dim3(1, 16, 2), 256>>>();

  k_invn2<<<(BATCH * 32) / 256, 256>>>(x);
  k_big<<<dim3(BATCH / BM, ND / BN), 256>>>(x, out);
}

// round 13
// speedup vs baseline: 1.3802x; 1.3802x over previous
#include <cuda_runtime.h>
#include <cuda_bf16.h>
#include <math.h>
#include <stdint.h>

#define ND     256
#define BATCH  65536
#define NROT   32640
#define NCHUNK 32
#define CLEN   (NROT / NCHUNK)   // 1020
#define MATSZ  (ND * ND)

// ---------------- device scratch (static allocation only; no cudaMalloc) ----
__device__ float2 g_cs[2][NROT];            // (cos, sin) per rotation, per matrix
__device__ uchar2 g_ij[NROT];               // (i, j) triu indices
__device__ float  g_pcs[2][ND];             // cos(phases), sin(phases)
__device__ float  g_bufA[2][NCHUNK][MATSZ]; // chunk matrices / tree ping
__device__ float  g_bufB[2][NCHUNK / 2][MATSZ]; // tree pong
__device__ float  g_PQ[2][MATSZ];           // P, Q stored row-major [m][n] (n = k dim)
__device__ float  g_invn2[BATCH];           // 1 / ||x_row||^2
// bf16 split operands for the tensor-core GEMM
__device__ __nv_bfloat16 g_xh[(size_t)BATCH * ND];
__device__ __nv_bfloat16 g_xl[(size_t)BATCH * ND];
__device__ __nv_bfloat16 g_Bh[2][MATSZ];    // hi(P), hi(Q)  row-major [m][n]
__device__ __nv_bfloat16 g_Bl[2][MATSZ];    // lo(P), lo(Q)

__device__ __forceinline__ int tri_off(int i) { return i * (2 * ND - i - 1) / 2; }

// ---------------- setup: triu indices + sincos of angles ---------------------
__global__ void k_setup(const float* __restrict__ r1, const float* __restrict__ r2,
                        const float* __restrict__ ph) {
  int k = blockIdx.x * blockDim.x + threadIdx.x;
  if (k < NROT) {
    float disc = (2.f * ND - 1.f) * (2.f * ND - 1.f) - 8.f * (float)k;
    int i = (int)floorf(((2.f * ND - 1.f) - sqrtf(fmaxf(disc, 0.f))) * 0.5f);
    if (i < 0) i = 0;
    if (i > ND - 2) i = ND - 2;
    while (i > 0 && tri_off(i) > k) i--;
    while (tri_off(i + 1) <= k) i++;
    int j = k - tri_off(i) + i + 1;
    g_ij[k] = make_uchar2((unsigned char)i, (unsigned char)j);
    float s, c;
    sincosf(r1[k], &s, &c); g_cs[0][k] = make_float2(c, s);
    sincosf(r2[k], &s, &c); g_cs[1][k] = make_float2(c, s);
  }
  if (k < ND) {
    float s, c;
    sincosf(ph[k], &s, &c);
    g_pcs[0][k] = c;
    g_pcs[1][k] = s;
  }
}

// ---------------- chunk kernel: apply CLEN Givens rotations to identity ------
__global__ void k_chunk() {
  __shared__ float sm[ND * 32];  // 32 KB static
  int t = threadIdx.x;           // 0..31
  int c = blockIdx.x, h = blockIdx.y, m = blockIdx.z;
  int col = (h << 5) + t;
#pragma unroll 8
  for (int r = 0; r < ND; r++) sm[(r << 5) + t] = (r == col) ? 1.f : 0.f;

  int k0 = c * CLEN, k1 = k0 + CLEN;
  int curi = g_ij[k0].x;
  float mi = sm[(curi << 5) + t];
  const float2* __restrict__ cs_arr = g_cs[m];
  for (int k = k0; k < k1; k++) {
    uchar2 ij = g_ij[k];
    float2 cs = cs_arr[k];
    int i = ij.x, j = ij.y;
    if (i != curi) {                 // uniform branch across warp
      sm[(curi << 5) + t] = mi;
      curi = i;
      mi = sm[(i << 5) + t];
    }
    float mj = sm[(j << 5) + t];
    sm[(j << 5) + t] = cs.y * mi + cs.x * mj;
    mi = cs.x * mi - cs.y * mj;
  }
  sm[(curi << 5) + t] = mi;

  float* o = g_bufA[m][c];
#pragma unroll 4
  for (int r = 0; r < ND; r++) o[r * ND + col] = sm[(r << 5) + t];
}

// ---------------- shared 256x256x256 GEMM tile (64x64 per block) -------------
__device__ __forceinline__ void gemm256_tile(const float* __restrict__ A,
                                             const float* __restrict__ B,
                                             float* __restrict__ D,
                                             const float* __restrict__ ks,
                                             int transD, int tile) {
  __shared__ float As[64][17];   // [m][k] padded
  __shared__ float Bs[16][68];   // [k][n] padded
  int m0 = (tile >> 2) << 6;
  int n0 = (tile & 3) << 6;
  int tid = threadIdx.x, tx = tid & 15, ty = tid >> 4;
  float acc[4][4] = {};
  for (int kk = 0; kk < ND; kk += 16) {
    int row = tid >> 2, kc = (tid & 3) << 2;
    float4 av = *(const float4*)(A + (m0 + row) * ND + kk + kc);
    if (ks) {
      av.x *= ks[kk + kc];     av.y *= ks[kk + kc + 1];
      av.z *= ks[kk + kc + 2]; av.w *= ks[kk + kc + 3];
    }
    As[row][kc] = av.x; As[row][kc + 1] = av.y;
    As[row][kc + 2] = av.z; As[row][kc + 3] = av.w;
    int kr = tid >> 4, nc = (tid & 15) << 2;
    *(float4*)&Bs[kr][nc] = *(const float4*)(B + (kk + kr) * ND + n0 + nc);
    __syncthreads();
#pragma unroll
    for (int k = 0; k < 16; k++) {
      float a[4];
#pragma unroll
      for (int r = 0; r < 4; r++) a[r] = As[ty * 4 + r][k];
      float4 b = *(float4*)&Bs[k][tx * 4];
#pragma unroll
      for (int r = 0; r < 4; r++) {
        acc[r][0] += a[r] * b.x; acc[r][1] += a[r] * b.y;
        acc[r][2] += a[r] * b.z; acc[r][3] += a[r] * b.w;
      }
    }
    __syncthreads();
  }
#pragma unroll
  for (int r = 0; r < 4; r++)
#pragma unroll
    for (int c = 0; c < 4; c++) {
      int mm = m0 + ty * 4 + r, nn = n0 + tx * 4 + c;
      if (!transD) D[mm * ND + nn] = acc[r][c];
      else         D[nn * ND + mm] = acc[r][c];
    }
}

// tree level: out[p] = in[2p+1] @ in[2p]
__global__ void k_gemm_tree(int level) {
  int p = blockIdx.x, tile = blockIdx.y, m = blockIdx.z;
  const float* in = (level & 1) ? &g_bufB[m][0][0] : &g_bufA[m][0][0];
  float* out      = (level & 1) ? &g_bufA[m][0][0] : &g_bufB[m][0][0];
  gemm256_tile(in + (size_t)(2 * p + 1) * MATSZ, in + (size_t)(2 * p) * MATSZ,
               out + (size_t)p * MATSZ, nullptr, 0, tile);
}

// P/Q: P = M2 @ diag(cos/sin phi) @ M1, stored ROW-MAJOR [m][n] (mma B operand)
__global__ void k_gemm_pq() {
  int tile = blockIdx.y, z = blockIdx.z;
  gemm256_tile(&g_bufB[1][0][0] /*M2*/, &g_bufB[0][0][0] /*M1*/,
               g_PQ[z], g_pcs[z], 0, tile);
}

// ---------------- inverse squared row norms ---------------------------------
__global__ void k_invn2(const float* __restrict__ x) {
  int warp = (blockIdx.x * blockDim.x + threadIdx.x) >> 5;
  int lane = threadIdx.x & 31;
  if (warp >= BATCH) return;
  const float4* xr = (const float4*)(x + (size_t)warp * ND);
  float s = 0.f;
#pragma unroll
  for (int it = 0; it < 2; it++) {
    float4 v = xr[lane + 32 * it];
    s += v.x * v.x + v.y * v.y + v.z * v.z + v.w * v.w;
  }
#pragma unroll
  for (int o = 16; o; o >>= 1) s += __shfl_xor_sync(0xffffffffu, s, o);
  if (lane == 0) g_invn2[warp] = 1.0f / s;
}

// ---------------- bf16 hi/lo split helpers -----------------------------------
__device__ __forceinline__ void split8(const float* __restrict__ src,
                                       __nv_bfloat16* __restrict__ h8,
                                       __nv_bfloat16* __restrict__ l8) {
#pragma unroll
  for (int e = 0; e < 8; e++) {
    float f = src[e];
    __nv_bfloat16 hb = __float2bfloat16_rn(f);
    h8[e] = hb;
    l8[e] = __float2bfloat16_rn(f - __bfloat162float(hb));
  }
}

// x -> xh, xl  (8 elems/thread, vectorized)
__global__ void k_splitX(const float* __restrict__ x) {
  size_t base = ((size_t)blockIdx.x * blockDim.x + threadIdx.x) * 8;
  float v[8];
  *(float4*)&v[0] = *(const float4*)(x + base);
  *(float4*)&v[4] = *(const float4*)(x + base + 4);
  __nv_bfloat16 h8[8], l8[8];
  split8(v, h8, l8);
  *(uint4*)(g_xh + base) = *(uint4*)h8;
  *(uint4*)(g_xl + base) = *(uint4*)l8;
}

// P,Q -> hi/lo bf16
__global__ void k_splitB() {
  size_t idx = ((size_t)blockIdx.x * blockDim.x + threadIdx.x) * 8;  // 0..2*MATSZ
  int z = idx >= MATSZ;
  size_t off = idx - (size_t)z * MATSZ;
  float v[8];
  *(float4*)&v[0] = *(const float4*)(&g_PQ[z][off]);
  *(float4*)&v[4] = *(const float4*)(&g_PQ[z][off + 4]);
  __nv_bfloat16 h8[8], l8[8];
  split8(v, h8, l8);
  *(uint4*)(&g_Bh[z][off]) = *(uint4*)h8;
  *(uint4*)(&g_Bl[z][off]) = *(uint4*)l8;
}

// ---------------- tensor-core big GEMM ---------------------------------------
// out[b][m] = invn2[b] * ( (x@P^T)[b][m]^2 + (x@Q^T)[b][m]^2 )
// y = x @ P^T with P row-major [m][n]: mma.row.col, A = x [b][k=n], B = P [m][k=n].
// Split: y ~= xh@Ph + xh@Pl + xl@Ph (xl@Pl dropped, ~2^-16).
#define MBM 128
#define MBN 64
#define MBK 32
#define APITCH 40   // bf16 pitch for smem tiles (conflict-free frag loads)

#define MMA_BF16(c, a, b)                                              \
  asm volatile(                                                        \
      "mma.sync.aligned.m16n8k16.row.col.f32.bf16.bf16.f32 "           \
      "{%0,%1,%2,%3}, {%4,%5,%6,%7}, {%8,%9}, {%0,%1,%2,%3};"          \
      : "+f"((c)[0]), "+f"((c)[1]), "+f"((c)[2]), "+f"((c)[3])         \
      : "r"((a)[0]), "r"((a)[1]), "r"((a)[2]), "r"((a)[3]),            \
        "r"((b)[0]), "r"((b)[1]))

__global__ __launch_bounds__(256) void k_big_mma(float* __restrict__ out) {
  __shared__ __nv_bfloat16 sAh[MBM * APITCH];      // 10 KB
  __shared__ __nv_bfloat16 sAl[MBM * APITCH];      // 10 KB
  __shared__ __nv_bfloat16 sB[4][MBN * APITCH];    // 4 x 5 KB  (ph, pl, qh, ql)

  int b0 = blockIdx.x * MBM;
  int n0 = blockIdx.y * MBN;
  int tid = threadIdx.x;
  int lane = tid & 31, warp = tid >> 5;
  int wm = warp & 3, wn = warp >> 2;       // 4 M-warps x 2 N-warps
  int g = lane >> 2, c2 = lane & 3;        // groupID, thread-in-group

  float accP[2][4][4] = {}, accQ[2][4][4] = {};

  for (int kk = 0; kk < ND; kk += MBK) {
    // --- stage A tiles (xh, xl): 128 rows x 32 k, uint4 = 8 bf16 ---
#pragma unroll
    for (int it = 0; it < 2; it++) {
      int idx = tid + 256 * it;            // 0..511
      int row = idx >> 2, seg = idx & 3;
      size_t gofs = (size_t)(b0 + row) * ND + kk + seg * 8;
      *(uint4*)(sAh + row * APITCH + seg * 8) = *(const uint4*)(g_xh + gofs);
      *(uint4*)(sAl + row * APITCH + seg * 8) = *(const uint4*)(g_xl + gofs);
    }
    // --- stage B tiles (ph, pl, qh, ql): 64 rows(m-out) x 32 k ---
    {
      int row = tid >> 2, seg = tid & 3;   // 0..63, 0..3
      size_t gofs = (size_t)(n0 + row) * ND + kk + seg * 8;
      *(uint4*)(sB[0] + row * APITCH + seg * 8) = *(const uint4*)(&g_Bh[0][gofs]);
      *(uint4*)(sB[1] + row * APITCH + seg * 8) = *(const uint4*)(&g_Bl[0][gofs]);
      *(uint4*)(sB[2] + row * APITCH + seg * 8) = *(const uint4*)(&g_Bh[1][gofs]);
      *(uint4*)(sB[3] + row * APITCH + seg * 8) = *(const uint4*)(&g_Bl[1][gofs]);
    }
    __syncthreads();

#pragma unroll
    for (int ks = 0; ks < 2; ks++) {
      int kb = ks * 16 + c2 * 2;           // bf16 col of this thread's pair
      // A fragments (2 m-tiles x 4 regs) for hi and lo
      uint32_t ah[2][4], al[2][4];
#pragma unroll
      for (int mt = 0; mt < 2; mt++) {
        int r = wm * 32 + mt * 16 + g;
        ah[mt][0] = *(const uint32_t*)(sAh + r * APITCH + kb);
        ah[mt][1] = *(const uint32_t*)(sAh + (r + 8) * APITCH + kb);
        ah[mt][2] = *(const uint32_t*)(sAh + r * APITCH + kb + 8);
        ah[mt][3] = *(const uint32_t*)(sAh + (r + 8) * APITCH + kb + 8);
        al[mt][0] = *(const uint32_t*)(sAl + r * APITCH + kb);
        al[mt][1] = *(const uint32_t*)(sAl + (r + 8) * APITCH + kb);
        al[mt][2] = *(const uint32_t*)(sAl + r * APITCH + kb + 8);
        al[mt][3] = *(const uint32_t*)(sAl + (r + 8) * APITCH + kb + 8);
      }
      // B fragments: [array][ntile][2]
      uint32_t bf[4][4][2];
#pragma unroll
      for (int a = 0; a < 4; a++)
#pragma unroll
        for (int nt = 0; nt < 4; nt++) {
          int n = wn * 32 + nt * 8 + g;
          bf[a][nt][0] = *(const uint32_t*)(sB[a] + n * APITCH + kb);
          bf[a][nt][1] = *(const uint32_t*)(sB[a] + n * APITCH + kb + 8);
        }
#pragma unroll
      for (int mt = 0; mt < 2; mt++)
#pragma unroll
        for (int nt = 0; nt < 4; nt++) {
          MMA_BF16(accP[mt][nt], ah[mt], bf[0][nt]);  // hh
          MMA_BF16(accP[mt][nt], ah[mt], bf[1][nt]);  // h*l
          MMA_BF16(accP[mt][nt], al[mt], bf[0][nt]);  // l*h
          MMA_BF16(accQ[mt][nt], ah[mt], bf[2][nt]);
          MMA_BF16(accQ[mt][nt], ah[mt], bf[3][nt]);
          MMA_BF16(accQ[mt][nt], al[mt], bf[2][nt]);
        }
    }
    __syncthreads();
  }

  // --- epilogue: out = invn2 * (p^2 + q^2) ---
#pragma unroll
  for (int mt = 0; mt < 2; mt++) {
    int r0 = b0 + wm * 32 + mt * 16 + g;
    float sc0 = g_invn2[r0];
    float sc1 = g_invn2[r0 + 8];
#pragma unroll
    for (int nt = 0; nt < 4; nt++) {
      int nc = n0 + wn * 32 + nt * 8 + c2 * 2;
      float p0 = accP[mt][nt][0], p1 = accP[mt][nt][1];
      float p2 = accP[mt][nt][2], p3 = accP[mt][nt][3];
      float q0 = accQ[mt][nt][0], q1 = accQ[mt][nt][1];
      float q2 = accQ[mt][nt][2], q3 = accQ[mt][nt][3];
      float2 o0 = make_float2((p0 * p0 + q0 * q0) * sc0,
                              (p1 * p1 + q1 * q1) * sc0);
      float2 o1 = make_float2((p2 * p2 + q2 * q2) * sc1,
                              (p3 * p3 + q3 * q3) * sc1);
      *(float2*)(out + (size_t)r0 * ND + nc) = o0;
      *(float2*)(out + (size_t)(r0 + 8) * ND + nc) = o1;
    }
  }
}

// ---------------- launch -----------------------------------------------------
extern "C" void kernel_launch(void* const* d_in, const int* in_sizes, int n_in,
                              void* d_out, int out_size) {
  const float* x     = (const float*)d_in[0];
  const float* rots1 = (const float*)d_in[1];
  const float* ph    = (const float*)d_in[2];
  const float* rots2 = (const float*)d_in[3];
  float* out = (float*)d_out;

  k_setup<<<(NROT + 255) / 256, 256>>>(rots1, rots2, ph);
  k_chunk<<<dim3(NCHUNK, 8, 2), 32>>>();

  int np = NCHUNK / 2, level = 0;
  while (np >= 1) {
    k_gemm_tree<<<dim3(np, 16, 2), 256>>>(level);
    np >>= 1;
    level++;
  }
  k_gemm_pq<<<dim3(1, 16, 2), 256>>>();
  k_splitB<<<(2 * MATSZ) / (256 * 8), 256>>>();

  k_invn2<<<(BATCH * 32) / 256, 256>>>(x);
  k_splitX<<<((size_t)BATCH * ND) / (256 * 8), 256>>>(x);
  k_big_mma<<<dim3(BATCH / MBM, ND / MBN), 256>>>(out);
}